// round 17
// baseline (speedup 1.0000x reference)
#include <cuda_runtime.h>
#include <cuda_fp16.h>
#include <cuda_bf16.h>
#include <cstdint>

// Problem constants (match reference_code)
#define N_NODES   100000
#define IN_DIM    256
#define OUT_DIM   64
#define KEEP_INV  (1.0f / 0.9f)
#define NBLK      ((N_NODES + 255) / 256)   // 391

// Padded-segment strides. Counts: x rows ~ Poisson(14.4) (P(>=64) ~1e-20),
// adj rows ~ Poisson(32) (P(>=96) ~1e-18 over all rows). Clamped defensively.
#define XSTRIDE   64
#define ASTRIDE   96

// ---------------------------------------------------------------------------
// Scratch (static device globals; no runtime allocation).  ~142 MB total.
// h is fp16: halves the spmm2 gather wavefronts vs fp32.
// ---------------------------------------------------------------------------
__device__ __align__(16) __half g_h[N_NODES * OUT_DIM];          // 12.8 MB
__device__ int  g_xcnt[N_NODES], g_acnt[N_NODES];
__device__ __align__(16) int2 g_pax[N_NODES * XSTRIDE];          // 51.2 MB
__device__ __align__(16) int2 g_paa[N_NODES * ASTRIDE];          // 76.8 MB

// ---------------------------------------------------------------------------
// 1) Zero per-row counters.
// ---------------------------------------------------------------------------
__global__ void zero_cnt_kernel() {
    int i = blockIdx.x * blockDim.x + threadIdx.x;
    if (i < N_NODES) { g_xcnt[i] = 0; g_acnt[i] = 0; }
}

// ---------------------------------------------------------------------------
// 2) FUSED CSR build: one pass. The count atomic's return value is the
//    element's final slot within its row's fixed-stride segment.
//    Blocks [0, xblocks) handle x; the rest handle adj.
//    Each thread takes 4 CONSECUTIVE elements -> int4/float4 streaming loads.
// ---------------------------------------------------------------------------
__global__ void __launch_bounds__(256) build_kernel(
        const float* __restrict__ x_vals, const int* __restrict__ x_rows,
        const int*   __restrict__ x_cols, const int* __restrict__ keep, int xnnz,
        const float* __restrict__ adj_vals, const int* __restrict__ adj_rows,
        const int*   __restrict__ adj_cols, int annz, int xblocks) {
    if ((int)blockIdx.x < xblocks) {
        int i0 = (blockIdx.x * 256 + threadIdx.x) * 4;
        int4 row, col, kp; float4 val;
        if (i0 + 3 < xnnz) {                    // vector path (LDG.128 x4)
            row = *(const int4*)  (x_rows + i0);
            col = *(const int4*)  (x_cols + i0);
            kp  = *(const int4*)  (keep   + i0);
            val = *(const float4*)(x_vals + i0);
        } else {                                // guarded scalar tail
            int r[4], cl[4], k[4]; float v[4];
            #pragma unroll
            for (int u = 0; u < 4; ++u) {
                int i = i0 + u;
                bool b = (i < xnnz);
                r[u] = b ? x_rows[i] : -1;
                k[u] = b ? keep[i]   : 0;
                cl[u] = b ? x_cols[i] : 0;
                v[u] = b ? x_vals[i] : 0.f;
            }
            row = make_int4(r[0], r[1], r[2], r[3]);
            col = make_int4(cl[0], cl[1], cl[2], cl[3]);
            kp  = make_int4(k[0], k[1], k[2], k[3]);
            val = make_float4(v[0], v[1], v[2], v[3]);
        }
        int   rr[4] = {row.x, row.y, row.z, row.w};
        int   cc[4] = {col.x, col.y, col.z, col.w};
        int   kk[4] = {kp.x,  kp.y,  kp.z,  kp.w};
        float vv[4] = {val.x, val.y, val.z, val.w};
        #pragma unroll
        for (int u = 0; u < 4; ++u) {
            if (rr[u] >= 0 && kk[u] != 0) {
                int rk = atomicAdd(&g_xcnt[rr[u]], 1);
                if (rk < XSTRIDE)
                    g_pax[rr[u] * XSTRIDE + rk] =
                        make_int2(cc[u], __float_as_int(vv[u] * KEEP_INV));
            }
        }
    } else {
        int i0 = (((int)blockIdx.x - xblocks) * 256 + threadIdx.x) * 4;
        int4 row, col; float4 val;
        if (i0 + 3 < annz) {
            row = *(const int4*)  (adj_rows + i0);
            col = *(const int4*)  (adj_cols + i0);
            val = *(const float4*)(adj_vals + i0);
        } else {
            int r[4], cl[4]; float v[4];
            #pragma unroll
            for (int u = 0; u < 4; ++u) {
                int i = i0 + u;
                bool b = (i < annz);
                r[u] = b ? adj_rows[i] : -1;
                cl[u] = b ? adj_cols[i] : 0;
                v[u] = b ? adj_vals[i] : 0.f;
            }
            row = make_int4(r[0], r[1], r[2], r[3]);
            col = make_int4(cl[0], cl[1], cl[2], cl[3]);
            val = make_float4(v[0], v[1], v[2], v[3]);
        }
        int   rr[4] = {row.x, row.y, row.z, row.w};
        int   cc[4] = {col.x, col.y, col.z, col.w};
        float vv[4] = {val.x, val.y, val.z, val.w};
        #pragma unroll
        for (int u = 0; u < 4; ++u) {
            if (rr[u] >= 0) {
                int rk = atomicAdd(&g_acnt[rr[u]], 1);
                if (rk < ASTRIDE)
                    g_paa[rr[u] * ASTRIDE + rk] =
                        make_int2(cc[u], __float_as_int(vv[u]));
            }
        }
    }
}

// ---------------------------------------------------------------------------
// 3) SpMM1: one warp per node; lane t owns outputs [2t, 2t+1].
//    Smem-staged edges read in PAIRS (int4 = 2 edges per LDS.128).
//    Tail is zero-padded to a multiple of 8 (stage is zero-filled, so
//    dummy edges contribute exactly 0) -> no serial tail loop.
// ---------------------------------------------------------------------------
__global__ void __launch_bounds__(256) spmm1_csr_kernel(const float* __restrict__ W) {
    __shared__ __align__(16) int2 stage[8][32];
    int wib  = threadIdx.x >> 5;                // warp index in block
    int warp = (blockIdx.x * blockDim.x + threadIdx.x) >> 5;
    int lane = threadIdx.x & 31;
    if (warp >= N_NODES) return;

    const float2* __restrict__ W2  = (const float2*)W;
    const int2*   __restrict__ seg = g_pax + warp * XSTRIDE;
    int c = min(g_xcnt[warp], XSTRIDE);
    float2 acc = make_float2(0.f, 0.f);

    for (int base = 0; base < c; base += 32) {
        int idx = base + lane;
        stage[wib][lane] = (idx < c) ? seg[idx] : make_int2(0, 0);
        __syncwarp();
        int m  = min(32, c - base);
        int mp = (m + 7) & ~7;                  // padded bound (zeros beyond m)
        const int4* st4 = (const int4*)stage[wib];
        for (int j0 = 0; j0 < mp; j0 += 8) {    // 8 edges = 4 int4 pairs
            #pragma unroll
            for (int q = 0; q < 4; ++q) {
                int4 e = st4[(j0 >> 1) + q];
                float2 w0 = W2[e.x * (OUT_DIM / 2) + lane];
                float2 w1 = W2[e.z * (OUT_DIM / 2) + lane];
                float v0 = __int_as_float(e.y), v1 = __int_as_float(e.w);
                acc.x = fmaf(v0, w0.x, acc.x); acc.y = fmaf(v0, w0.y, acc.y);
                acc.x = fmaf(v1, w1.x, acc.x); acc.y = fmaf(v1, w1.y, acc.y);
            }
        }
        __syncwarp();
    }
    reinterpret_cast<__half2*>(g_h)[warp * (OUT_DIM / 2) + lane] = __float22half2_rn(acc);
}

// ---------------------------------------------------------------------------
// 4) SpMM2 + fused ReLU: same paired + zero-padded structure; h fp16.
//    out[n,:] = relu( sum_e a_e * h[col_e,:] )
// ---------------------------------------------------------------------------
__global__ void __launch_bounds__(256) spmm2_csr_kernel(float* __restrict__ out) {
    __shared__ __align__(16) int2 stage[8][32];
    int wib  = threadIdx.x >> 5;
    int warp = (blockIdx.x * blockDim.x + threadIdx.x) >> 5;
    int lane = threadIdx.x & 31;
    if (warp >= N_NODES) return;

    const __half2* __restrict__ hp  = (const __half2*)g_h;
    const int2*    __restrict__ seg = g_paa + warp * ASTRIDE;
    int c = min(g_acnt[warp], ASTRIDE);
    float2 acc = make_float2(0.f, 0.f);

    for (int base = 0; base < c; base += 32) {
        int idx = base + lane;
        stage[wib][lane] = (idx < c) ? seg[idx] : make_int2(0, 0);
        __syncwarp();
        int m  = min(32, c - base);
        int mp = (m + 7) & ~7;                  // padded bound (zeros beyond m)
        const int4* st4 = (const int4*)stage[wib];
        for (int j0 = 0; j0 < mp; j0 += 8) {    // 8 edges = 4 int4 pairs
            #pragma unroll
            for (int q = 0; q < 4; ++q) {
                int4 e = st4[(j0 >> 1) + q];
                float2 h0 = __half22float2(hp[e.x * (OUT_DIM / 2) + lane]);
                float2 h1 = __half22float2(hp[e.z * (OUT_DIM / 2) + lane]);
                float v0 = __int_as_float(e.y), v1 = __int_as_float(e.w);
                acc.x = fmaf(v0, h0.x, acc.x); acc.y = fmaf(v0, h0.y, acc.y);
                acc.x = fmaf(v1, h1.x, acc.x); acc.y = fmaf(v1, h1.y, acc.y);
            }
        }
        __syncwarp();
    }
    acc.x = fmaxf(acc.x, 0.f);
    acc.y = fmaxf(acc.y, 0.f);
    reinterpret_cast<float2*>(out)[warp * (OUT_DIM / 2) + lane] = acc;
}

// ---------------------------------------------------------------------------
// Input order: 0 x_vals, 1 x_rows, 2 x_cols, 3 adj_vals, 4 adj_rows,
//              5 adj_cols, 6 W, 7 keep_mask(int32)
// ---------------------------------------------------------------------------
extern "C" void kernel_launch(void* const* d_in, const int* in_sizes, int n_in,
                              void* d_out, int out_size) {
    if (n_in < 8) return;

    const float* x_vals   = (const float*)d_in[0];
    const int*   x_rows   = (const int*)  d_in[1];
    const int*   x_cols   = (const int*)  d_in[2];
    const float* adj_vals = (const float*)d_in[3];
    const int*   adj_rows = (const int*)  d_in[4];
    const int*   adj_cols = (const int*)  d_in[5];
    const float* W        = (const float*)d_in[6];
    const int*   keep     = (const int*)  d_in[7];

    const int x_nnz = in_sizes[0];
    const int a_nnz = in_sizes[3];
    float* out = (float*)d_out;

    const int T = 256;
    int xblocks = (x_nnz + 1023) / 1024;        // 4 consecutive elements/thread
    int ablocks = (a_nnz + 1023) / 1024;

    // Fused CSR build (2 launches total before the SpMMs)
    zero_cnt_kernel<<<NBLK, T>>>();
    build_kernel<<<xblocks + ablocks, T>>>(x_vals, x_rows, x_cols, keep, x_nnz,
                                           adj_vals, adj_rows, adj_cols, a_nnz,
                                           xblocks);

    // Gather-reduce SpMMs (one warp per node; 8 warps per block)
    int warp_blocks = (N_NODES * 32 + T - 1) / T;
    spmm1_csr_kernel<<<warp_blocks, T>>>(W);
    spmm2_csr_kernel<<<warp_blocks, T>>>(out);
}